// round 10
// baseline (speedup 1.0000x reference)
#include <cuda_runtime.h>
#include <cstdint>

#define L    64      // steps per chunk
#define KCH  256     // chunks per batch (T / L)
#define MAXB 256
#define OVLG 2       // overlap groups (8 warm-up steps)
#define CPB  128     // chunks (threads) per block
#define RS   36      // smem row stride in floats (32 data + 4 pad)
#define NG   (OVLG + L / 4)   // 18 groups
#define NSTG 3       // cp.async pipeline stages

__device__ float g_bc[MAXB * 2];   // per-block log-growth partial
__device__ float g_bs[MAXB * 2];   // per-block score partial
__device__ int   g_bn[MAXB * 2];   // per-block masked count partial
__device__ float g_nf[MAXB * 8];   // normalized final alpha direction

// ---- packed f32x2 helpers ---------------------------------------------------
__device__ __forceinline__ unsigned long long pk2(float lo, float hi) {
    unsigned long long r;
    asm("mov.b64 %0, {%1, %2};" : "=l"(r) : "f"(lo), "f"(hi));
    return r;
}
__device__ __forceinline__ void upk2(unsigned long long v, float& lo, float& hi) {
    asm("mov.b64 {%0, %1}, %2;" : "=f"(lo), "=f"(hi) : "l"(v));
}
__device__ __forceinline__ unsigned long long mul2(unsigned long long a, unsigned long long b) {
    unsigned long long r;
    asm("mul.rn.f32x2 %0, %1, %2;" : "=l"(r) : "l"(a), "l"(b));
    return r;
}
__device__ __forceinline__ unsigned long long fma2(unsigned long long a, unsigned long long b,
                                                   unsigned long long c) {
    unsigned long long r;
    asm("fma.rn.f32x2 %0, %1, %2, %3;" : "=l"(r) : "l"(a), "l"(b), "l"(c));
    return r;
}

// ---- cp.async helpers -------------------------------------------------------
__device__ __forceinline__ void cp16(uint32_t dst, const void* src) {
    asm volatile("cp.async.ca.shared.global [%0], [%1], 16;" :: "r"(dst), "l"(src));
}
__device__ __forceinline__ void cp_commit() {
    asm volatile("cp.async.commit_group;" ::: "memory");
}
template<int N> __device__ __forceinline__ void cp_wait() {
    asm volatile("cp.async.wait_group %0;" :: "n"(N) : "memory");
}

// v <- (v^T M) ∘ exp(e)
__device__ __forceinline__ void vstep(float v[8], const unsigned long long M2[8][4],
                                      const float e[8])
{
    unsigned long long ev0 = pk2(__expf(e[0]), __expf(e[1]));
    unsigned long long ev1 = pk2(__expf(e[2]), __expf(e[3]));
    unsigned long long ev2 = pk2(__expf(e[4]), __expf(e[5]));
    unsigned long long ev3 = pk2(__expf(e[6]), __expf(e[7]));

    unsigned long long vb = pk2(v[0], v[0]);
    unsigned long long a0 = mul2(vb, M2[0][0]);
    unsigned long long a1 = mul2(vb, M2[0][1]);
    unsigned long long a2 = mul2(vb, M2[0][2]);
    unsigned long long a3 = mul2(vb, M2[0][3]);
#pragma unroll
    for (int i = 1; i < 8; i++) {
        vb = pk2(v[i], v[i]);
        a0 = fma2(vb, M2[i][0], a0);
        a1 = fma2(vb, M2[i][1], a1);
        a2 = fma2(vb, M2[i][2], a2);
        a3 = fma2(vb, M2[i][3], a3);
    }
    a0 = mul2(a0, ev0);
    a1 = mul2(a1, ev1);
    a2 = mul2(a2, ev2);
    a3 = mul2(a3, ev3);
    upk2(a0, v[0], v[1]);
    upk2(a1, v[2], v[3]);
    upk2(a2, v[4], v[5]);
    upk2(a3, v[6], v[7]);
}

// ---------------------------------------------------------------------------
// Kernel 1: thread = chunk. Vector recurrence, 8-step overlap warm-up,
// 3-stage cp.async staging, fused score, block-level (c,sp,cnt) reduce.
// ---------------------------------------------------------------------------
__global__ void __launch_bounds__(CPB) crf_chunk_vec(
    const float* __restrict__ em,
    const int* __restrict__ tags,
    const int* __restrict__ mask,
    const float* __restrict__ trans,
    const float* __restrict__ startt,
    int B, int T)
{
    extern __shared__ float sE[];   // NSTG * CPB * RS floats

    int tid = threadIdx.x;
    int b   = blockIdx.x >> 1;
    int k0  = (blockIdx.x & 1) * CPB;
    int k   = k0 + tid;
    size_t bT = (size_t)b * T;
    const float* emB = em + bT * 8;

    // this thread's 8 staging slots (fixed geometry)
    int srow[8], sqq[8];
#pragma unroll
    for (int m = 0; m < 8; m++) {
        int idx = m * CPB + tid;
        srow[m] = idx >> 3;
        sqq[m]  = idx & 7;
    }

    // issue tile gg into buffer gg % NSTG
    auto issue_tile = [&](int gg) {
        int g = gg - OVLG;
        float* buf = sE + (gg % NSTG) * (CPB * RS);
#pragma unroll
        for (int m = 0; m < 8; m++) {
            int tr = (k0 + srow[m]) * L + 4 * g;
            if (tr < 0) tr = 0;
            uint32_t dst = (uint32_t)__cvta_generic_to_shared(
                buf + srow[m] * RS + sqq[m] * 4);
            cp16(dst, emB + (size_t)tr * 8 + sqq[m] * 4);
        }
    };

    unsigned long long M2[8][4];
#pragma unroll
    for (int i = 0; i < 8; i++)
#pragma unroll
        for (int jj = 0; jj < 4; jj++)
            M2[i][jj] = pk2(__expf(__ldg(&trans[i * 8 + 2 * jj])),
                            __expf(__ldg(&trans[i * 8 + 2 * jj + 1])));

    float v[8];
#pragma unroll
    for (int j = 0; j < 8; j++) v[j] = 0.125f;

    float c = 0.0f, sp = 0.0f;
    int mcnt = 0;
    int pv = __ldg(&tags[bT + (k > 0 ? k * L - 1 : 0)]);

    // prologue: issue NSTG-1 tiles
    issue_tile(0); cp_commit();
    issue_tile(1); cp_commit();

    for (int gg = 0; gg < NG; gg++) {
        int g = gg - OVLG;

        if (gg + 1 < NG) cp_wait<1>(); else cp_wait<0>();
        __syncthreads();

        const float* erow = sE + (gg % NSTG) * (CPB * RS) + tid * RS;
        int tb = k * L + 4 * g;

        if (g == 0) {
            if (k == 0) {
                float e0[8];
                *(float4*)(e0)     = *((const float4*)erow);
                *(float4*)(e0 + 4) = *((const float4*)erow + 1);
                float s = 0.0f;
#pragma unroll
                for (int j = 0; j < 8; j++) {
                    v[j] = __expf(__ldg(&startt[j]) + e0[j]);
                    s += v[j];
                }
                c = __logf(s);
                float r = __fdividef(1.0f, s);
#pragma unroll
                for (int j = 0; j < 8; j++) v[j] *= r;
            } else {
                float s = v[0]+v[1]+v[2]+v[3]+v[4]+v[5]+v[6]+v[7];
                float r = __fdividef(1.0f, s);
                c = 0.0f;
#pragma unroll
                for (int j = 0; j < 8; j++) v[j] *= r;
            }
        }

        if (g >= 0) {
            int4 tg4 = __ldg((const int4*)(tags + bT + tb));
            int4 mk4 = __ldg((const int4*)(mask + bT + tb));
            int tgA[4] = {tg4.x, tg4.y, tg4.z, tg4.w};
            int mkA[4] = {mk4.x, mk4.y, mk4.z, mk4.w};
#pragma unroll
            for (int q = 0; q < 4; q++) {
                float e[8];
                *(float4*)(e)     = *((const float4*)erow + 2 * q);
                *(float4*)(e + 4) = *((const float4*)erow + 2 * q + 1);
                int tg = tgA[q];
                if (mkA[q] && (tb + q >= 1)) {
                    vstep(v, M2, e);
                    float es = e[0];
#pragma unroll
                    for (int j = 1; j < 8; j++) es = (tg == j) ? e[j] : es;
                    sp += es + __ldg(&trans[pv * 8 + tg]);
                    mcnt++;
                }
                pv = tg;
            }
        } else if (tb >= 0) {   // warm-up (k>0 only)
            int4 mk4 = __ldg((const int4*)(mask + bT + tb));
            int mkA[4] = {mk4.x, mk4.y, mk4.z, mk4.w};
#pragma unroll
            for (int q = 0; q < 4; q++) {
                float e[8];
                *(float4*)(e)     = *((const float4*)erow + 2 * q);
                *(float4*)(e + 4) = *((const float4*)erow + 2 * q + 1);
                if (mkA[q]) vstep(v, M2, e);
            }
        }

        // group-end rescale
        {
            float s = v[0]+v[1]+v[2]+v[3]+v[4]+v[5]+v[6]+v[7];
            float r = __fdividef(1.0f, s);
            c += __logf(s);
#pragma unroll
            for (int j = 0; j < 8; j++) v[j] *= r;
        }

        // issue tile gg+NSTG-1 into the buffer freed by tile gg-1
        if (gg + NSTG - 1 < NG) { issue_tile(gg + NSTG - 1); cp_commit(); }
    }

    // final alpha direction for the last chunk
    if (k == KCH - 1) {
#pragma unroll
        for (int j = 0; j < 8; j++) g_nf[b * 8 + j] = v[j];
    }

    // --- block-level reduction of (c, sp, cnt), reusing staging smem ---
    __syncthreads();
    float* rC = sE;
    float* rS = sE + CPB;
    int*   rN = (int*)(sE + 2 * CPB);
    rC[tid] = c; rS[tid] = sp; rN[tid] = mcnt;
    __syncthreads();
#pragma unroll
    for (int s = CPB / 2; s > 0; s >>= 1) {
        if (tid < s) {
            rC[tid] += rC[tid + s];
            rS[tid] += rS[tid + s];
            rN[tid] += rN[tid + s];
        }
        __syncthreads();
    }
    if (tid == 0) {
        g_bc[blockIdx.x] = rC[0];
        g_bs[blockIdx.x] = rS[0];
        g_bn[blockIdx.x] = rN[0];
    }
}

// ---------------------------------------------------------------------------
// Kernel 2: thread per batch. Combine 2 block partials, end term, NLL.
// ---------------------------------------------------------------------------
__global__ void __launch_bounds__(128) crf_final(
    const float* __restrict__ em,
    const int* __restrict__ tags,
    const int* __restrict__ mask,
    const float* __restrict__ startt,
    const float* __restrict__ endt,
    float* __restrict__ out,
    int B, int T)
{
    int b = blockIdx.x * blockDim.x + threadIdx.x;
    if (b >= B) return;
    size_t bT = (size_t)b * T;

    float c  = g_bc[2 * b] + g_bc[2 * b + 1];
    float sp = g_bs[2 * b] + g_bs[2 * b + 1];
    int  cnt = g_bn[2 * b] + g_bn[2 * b + 1];

    float vsum = 0.0f;
#pragma unroll
    for (int j = 0; j < 8; j++)
        vsum += g_nf[b * 8 + j] * __expf(__ldg(&endt[j]));
    float logZ = c + __logf(vsum);

    cnt += (__ldg(&mask[bT]) != 0) ? 1 : 0;
    int last_valid = cnt - 1;
    int tag0  = __ldg(&tags[bT]);
    int lastt = __ldg(&tags[bT + last_valid]);
    float score = __ldg(&startt[tag0]) + __ldg(&em[bT * 8 + tag0])
                + sp + __ldg(&endt[lastt]);
    out[b] = logZ - score;
}

// ---------------------------------------------------------------------------
extern "C" void kernel_launch(void* const* d_in, const int* in_sizes, int n_in,
                              void* d_out, int out_size)
{
    const float* em     = (const float*)d_in[0];
    const int*   tags   = (const int*)d_in[1];
    const int*   mask   = (const int*)d_in[2];
    const float* trans  = (const float*)d_in[3];
    const float* startt = (const float*)d_in[4];
    const float* endt   = (const float*)d_in[5];

    int B = out_size;                 // 256
    int T = in_sizes[0] / (B * 8);    // 16384 (= KCH * L)

    int smem = NSTG * CPB * RS * sizeof(float);   // 55296 B
    cudaFuncSetAttribute(crf_chunk_vec,
                         cudaFuncAttributeMaxDynamicSharedMemorySize, smem);

    int nblocks = B * (KCH / CPB);    // 512
    crf_chunk_vec<<<nblocks, CPB, smem>>>(em, tags, mask, trans, startt, B, T);

    crf_final<<<(B + 127) / 128, 128>>>(em, tags, mask, startt, endt,
                                        (float*)d_out, B, T);
}

// round 11
// speedup vs baseline: 1.0324x; 1.0324x over previous
#include <cuda_runtime.h>

#define L    64      // steps per chunk
#define KCH  256     // chunks per batch (T / L)
#define MAXB 256
#define OVLG 2       // overlap groups (8 warm-up steps)
#define CPB  128     // chunks (threads) per block
#define RS   36      // smem row stride in floats (32 data + 4 pad)

__device__ float g_bc[MAXB * 2];   // per-block log-growth partial
__device__ float g_bs[MAXB * 2];   // per-block score partial
__device__ int   g_bn[MAXB * 2];   // per-block masked count partial
__device__ float g_nf[MAXB * 8];   // normalized final alpha direction

// ---- packed f32x2 helpers ---------------------------------------------------
__device__ __forceinline__ unsigned long long pk2(float lo, float hi) {
    unsigned long long r;
    asm("mov.b64 %0, {%1, %2};" : "=l"(r) : "f"(lo), "f"(hi));
    return r;
}
__device__ __forceinline__ void upk2(unsigned long long v, float& lo, float& hi) {
    asm("mov.b64 {%0, %1}, %2;" : "=f"(lo), "=f"(hi) : "l"(v));
}
__device__ __forceinline__ unsigned long long mul2(unsigned long long a, unsigned long long b) {
    unsigned long long r;
    asm("mul.rn.f32x2 %0, %1, %2;" : "=l"(r) : "l"(a), "l"(b));
    return r;
}
__device__ __forceinline__ unsigned long long fma2(unsigned long long a, unsigned long long b,
                                                   unsigned long long c) {
    unsigned long long r;
    asm("fma.rn.f32x2 %0, %1, %2, %3;" : "=l"(r) : "l"(a), "l"(b), "l"(c));
    return r;
}

// v <- (v^T M) ∘ exp(e)
__device__ __forceinline__ void vstep(float v[8], const unsigned long long M2[8][4],
                                      const float e[8])
{
    unsigned long long ev0 = pk2(__expf(e[0]), __expf(e[1]));
    unsigned long long ev1 = pk2(__expf(e[2]), __expf(e[3]));
    unsigned long long ev2 = pk2(__expf(e[4]), __expf(e[5]));
    unsigned long long ev3 = pk2(__expf(e[6]), __expf(e[7]));

    unsigned long long vb = pk2(v[0], v[0]);
    unsigned long long a0 = mul2(vb, M2[0][0]);
    unsigned long long a1 = mul2(vb, M2[0][1]);
    unsigned long long a2 = mul2(vb, M2[0][2]);
    unsigned long long a3 = mul2(vb, M2[0][3]);
#pragma unroll
    for (int i = 1; i < 8; i++) {
        vb = pk2(v[i], v[i]);
        a0 = fma2(vb, M2[i][0], a0);
        a1 = fma2(vb, M2[i][1], a1);
        a2 = fma2(vb, M2[i][2], a2);
        a3 = fma2(vb, M2[i][3], a3);
    }
    a0 = mul2(a0, ev0);
    a1 = mul2(a1, ev1);
    a2 = mul2(a2, ev2);
    a3 = mul2(a3, ev3);
    upk2(a0, v[0], v[1]);
    upk2(a1, v[2], v[3]);
    upk2(a2, v[4], v[5]);
    upk2(a3, v[6], v[7]);
}

// ---------------------------------------------------------------------------
// Kernel 1: thread = chunk. Vector recurrence with 8-step overlap warm-up.
// Double-buffered LDG->reg->STS staging (R9, proven), one syncthreads per
// group; block-level (c, sp, cnt) reduction at the end (R10's one good bit).
// ---------------------------------------------------------------------------
__global__ void __launch_bounds__(CPB) crf_chunk_vec(
    const float* __restrict__ em,
    const int* __restrict__ tags,
    const int* __restrict__ mask,
    const float* __restrict__ trans,
    const float* __restrict__ startt,
    int B, int T)
{
    __shared__ float sE[2][CPB * RS];

    int tid = threadIdx.x;
    int b   = blockIdx.x >> 1;
    int k0  = (blockIdx.x & 1) * CPB;
    int k   = k0 + tid;
    size_t bT = (size_t)b * T;
    const float* emB = em + bT * 8;

    unsigned long long M2[8][4];
#pragma unroll
    for (int i = 0; i < 8; i++)
#pragma unroll
        for (int jj = 0; jj < 4; jj++)
            M2[i][jj] = pk2(__expf(__ldg(&trans[i * 8 + 2 * jj])),
                            __expf(__ldg(&trans[i * 8 + 2 * jj + 1])));

    float v[8];
#pragma unroll
    for (int j = 0; j < 8; j++) v[j] = 0.125f;

    float c = 0.0f, sp = 0.0f;
    int mcnt = 0;
    int pv = __ldg(&tags[bT + (k > 0 ? k * L - 1 : 0)]);

    float4 stg[8];
    // preload first tile (g = -OVLG)
#pragma unroll
    for (int m = 0; m < 8; m++) {
        int idx = m * CPB + tid;
        int r   = idx >> 3;
        int qq  = idx & 7;
        int tr  = (k0 + r) * L + 4 * (-OVLG);
        if (tr < 0) tr = 0;
        stg[m] = __ldg((const float4*)(emB + (size_t)tr * 8) + qq);
    }
#pragma unroll
    for (int m = 0; m < 8; m++) {
        int idx = m * CPB + tid;
        *((float4*)(sE[0] + (idx >> 3) * RS) + (idx & 7)) = stg[m];
    }
    __syncthreads();

    for (int g = -OVLG; g < L / 4; g++) {
        int cur = (g + OVLG) & 1;

        // issue next tile's LDGs before compute (latency hidden under compute)
        bool more = (g + 1 < L / 4);
        if (more) {
#pragma unroll
            for (int m = 0; m < 8; m++) {
                int idx = m * CPB + tid;
                int r   = idx >> 3;
                int qq  = idx & 7;
                int tr  = (k0 + r) * L + 4 * (g + 1);
                if (tr < 0) tr = 0;
                stg[m] = __ldg((const float4*)(emB + (size_t)tr * 8) + qq);
            }
        }

        int tb = k * L + 4 * g;
        const float* erow = sE[cur] + tid * RS;

        if (g == 0) {
            if (k == 0) {
                float e0[8];
                *(float4*)(e0)     = *((const float4*)erow);
                *(float4*)(e0 + 4) = *((const float4*)erow + 1);
                float s = 0.0f;
#pragma unroll
                for (int j = 0; j < 8; j++) {
                    v[j] = __expf(__ldg(&startt[j]) + e0[j]);
                    s += v[j];
                }
                c = __logf(s);
                float r = __fdividef(1.0f, s);
#pragma unroll
                for (int j = 0; j < 8; j++) v[j] *= r;
            } else {
                float s = v[0]+v[1]+v[2]+v[3]+v[4]+v[5]+v[6]+v[7];
                float r = __fdividef(1.0f, s);
                c = 0.0f;
#pragma unroll
                for (int j = 0; j < 8; j++) v[j] *= r;
            }
        }

        if (g >= 0) {
            int4 tg4 = __ldg((const int4*)(tags + bT + tb));
            int4 mk4 = __ldg((const int4*)(mask + bT + tb));
            int tgA[4] = {tg4.x, tg4.y, tg4.z, tg4.w};
            int mkA[4] = {mk4.x, mk4.y, mk4.z, mk4.w};
#pragma unroll
            for (int q = 0; q < 4; q++) {
                float e[8];
                *(float4*)(e)     = *((const float4*)erow + 2 * q);
                *(float4*)(e + 4) = *((const float4*)erow + 2 * q + 1);
                int tg = tgA[q];
                if (mkA[q] && (tb + q >= 1)) {
                    vstep(v, M2, e);
                    float es = e[0];
#pragma unroll
                    for (int j = 1; j < 8; j++) es = (tg == j) ? e[j] : es;
                    sp += es + __ldg(&trans[pv * 8 + tg]);
                    mcnt++;
                }
                pv = tg;
            }
        } else if (tb >= 0) {   // warm-up (k>0 only)
            int4 mk4 = __ldg((const int4*)(mask + bT + tb));
            int mkA[4] = {mk4.x, mk4.y, mk4.z, mk4.w};
#pragma unroll
            for (int q = 0; q < 4; q++) {
                float e[8];
                *(float4*)(e)     = *((const float4*)erow + 2 * q);
                *(float4*)(e + 4) = *((const float4*)erow + 2 * q + 1);
                if (mkA[q]) vstep(v, M2, e);
            }
        }

        // group-end rescale
        {
            float s = v[0]+v[1]+v[2]+v[3]+v[4]+v[5]+v[6]+v[7];
            float r = __fdividef(1.0f, s);
            c += __logf(s);
#pragma unroll
            for (int j = 0; j < 8; j++) v[j] *= r;
        }

        // store next tile into the alternate buffer, then one sync
        if (more) {
#pragma unroll
            for (int m = 0; m < 8; m++) {
                int idx = m * CPB + tid;
                *((float4*)(sE[cur ^ 1] + (idx >> 3) * RS) + (idx & 7)) = stg[m];
            }
            __syncthreads();
        }
    }

    // final alpha direction for the last chunk
    if (k == KCH - 1) {
#pragma unroll
        for (int j = 0; j < 8; j++) g_nf[b * 8 + j] = v[j];
    }

    // --- block-level reduction of (c, sp, cnt), reusing staging smem ---
    __syncthreads();
    float* rC = sE[0];
    float* rS = sE[0] + CPB;
    int*   rN = (int*)(sE[0] + 2 * CPB);
    rC[tid] = c; rS[tid] = sp; rN[tid] = mcnt;
    __syncthreads();
#pragma unroll
    for (int s = CPB / 2; s > 0; s >>= 1) {
        if (tid < s) {
            rC[tid] += rC[tid + s];
            rS[tid] += rS[tid + s];
            rN[tid] += rN[tid + s];
        }
        __syncthreads();
    }
    if (tid == 0) {
        g_bc[blockIdx.x] = rC[0];
        g_bs[blockIdx.x] = rS[0];
        g_bn[blockIdx.x] = rN[0];
    }
}

// ---------------------------------------------------------------------------
// Kernel 2: thread per batch. Combine 2 block partials, end term, NLL.
// ---------------------------------------------------------------------------
__global__ void __launch_bounds__(128) crf_final(
    const float* __restrict__ em,
    const int* __restrict__ tags,
    const int* __restrict__ mask,
    const float* __restrict__ startt,
    const float* __restrict__ endt,
    float* __restrict__ out,
    int B, int T)
{
    int b = blockIdx.x * blockDim.x + threadIdx.x;
    if (b >= B) return;
    size_t bT = (size_t)b * T;

    float c  = g_bc[2 * b] + g_bc[2 * b + 1];
    float sp = g_bs[2 * b] + g_bs[2 * b + 1];
    int  cnt = g_bn[2 * b] + g_bn[2 * b + 1];

    float vsum = 0.0f;
#pragma unroll
    for (int j = 0; j < 8; j++)
        vsum += g_nf[b * 8 + j] * __expf(__ldg(&endt[j]));
    float logZ = c + __logf(vsum);

    cnt += (__ldg(&mask[bT]) != 0) ? 1 : 0;
    int last_valid = cnt - 1;
    int tag0  = __ldg(&tags[bT]);
    int lastt = __ldg(&tags[bT + last_valid]);
    float score = __ldg(&startt[tag0]) + __ldg(&em[bT * 8 + tag0])
                + sp + __ldg(&endt[lastt]);
    out[b] = logZ - score;
}

// ---------------------------------------------------------------------------
extern "C" void kernel_launch(void* const* d_in, const int* in_sizes, int n_in,
                              void* d_out, int out_size)
{
    const float* em     = (const float*)d_in[0];
    const int*   tags   = (const int*)d_in[1];
    const int*   mask   = (const int*)d_in[2];
    const float* trans  = (const float*)d_in[3];
    const float* startt = (const float*)d_in[4];
    const float* endt   = (const float*)d_in[5];

    int B = out_size;                 // 256
    int T = in_sizes[0] / (B * 8);    // 16384 (= KCH * L)

    int nblocks = B * (KCH / CPB);    // 512
    crf_chunk_vec<<<nblocks, CPB>>>(em, tags, mask, trans, startt, B, T);

    crf_final<<<(B + 127) / 128, 128>>>(em, tags, mask, startt, endt,
                                        (float*)d_out, B, T);
}

// round 12
// speedup vs baseline: 1.3180x; 1.2766x over previous
#include <cuda_runtime.h>

#define L    64      // steps per chunk
#define KCH  256     // chunks per batch (T / L)
#define MAXB 256
#define OVLG 2       // overlap groups (8 warm-up steps)
#define CPB  128     // chunks (threads) per block
#define RS   36      // smem row stride in floats (32 data + 4 pad)

__device__ float g_c  [MAXB * KCH];   // per-chunk log-growth
__device__ float g_sp [MAXB * KCH];   // per-chunk score partial
__device__ int   g_cnt[MAXB * KCH];   // per-chunk masked count (t>=1)
__device__ float g_nf [MAXB * 8];     // normalized final alpha direction

// ---- packed f32x2 helpers ---------------------------------------------------
__device__ __forceinline__ unsigned long long pk2(float lo, float hi) {
    unsigned long long r;
    asm("mov.b64 %0, {%1, %2};" : "=l"(r) : "f"(lo), "f"(hi));
    return r;
}
__device__ __forceinline__ void upk2(unsigned long long v, float& lo, float& hi) {
    asm("mov.b64 {%0, %1}, %2;" : "=f"(lo), "=f"(hi) : "l"(v));
}
__device__ __forceinline__ unsigned long long mul2(unsigned long long a, unsigned long long b) {
    unsigned long long r;
    asm("mul.rn.f32x2 %0, %1, %2;" : "=l"(r) : "l"(a), "l"(b));
    return r;
}
__device__ __forceinline__ unsigned long long fma2(unsigned long long a, unsigned long long b,
                                                   unsigned long long c) {
    unsigned long long r;
    asm("fma.rn.f32x2 %0, %1, %2, %3;" : "=l"(r) : "l"(a), "l"(b), "l"(c));
    return r;
}

// v <- (v^T M) ∘ exp(e)
__device__ __forceinline__ void vstep(float v[8], const unsigned long long M2[8][4],
                                      const float e[8])
{
    unsigned long long ev0 = pk2(__expf(e[0]), __expf(e[1]));
    unsigned long long ev1 = pk2(__expf(e[2]), __expf(e[3]));
    unsigned long long ev2 = pk2(__expf(e[4]), __expf(e[5]));
    unsigned long long ev3 = pk2(__expf(e[6]), __expf(e[7]));

    unsigned long long vb = pk2(v[0], v[0]);
    unsigned long long a0 = mul2(vb, M2[0][0]);
    unsigned long long a1 = mul2(vb, M2[0][1]);
    unsigned long long a2 = mul2(vb, M2[0][2]);
    unsigned long long a3 = mul2(vb, M2[0][3]);
#pragma unroll
    for (int i = 1; i < 8; i++) {
        vb = pk2(v[i], v[i]);
        a0 = fma2(vb, M2[i][0], a0);
        a1 = fma2(vb, M2[i][1], a1);
        a2 = fma2(vb, M2[i][2], a2);
        a3 = fma2(vb, M2[i][3], a3);
    }
    a0 = mul2(a0, ev0);
    a1 = mul2(a1, ev1);
    a2 = mul2(a2, ev2);
    a3 = mul2(a3, ev3);
    upk2(a0, v[0], v[1]);
    upk2(a1, v[2], v[3]);
    upk2(a2, v[4], v[5]);
    upk2(a3, v[6], v[7]);
}

// ---------------------------------------------------------------------------
// Kernel 1: IDENTICAL to the 55.1us R9 champion. Thread = chunk; vector
// recurrence, 8-step overlap warm-up, double-buffered LDG->reg->STS staging,
// one syncthreads per group, per-chunk (c, sp, cnt) array writes.
// ---------------------------------------------------------------------------
__global__ void __launch_bounds__(CPB) crf_chunk_vec(
    const float* __restrict__ em,
    const int* __restrict__ tags,
    const int* __restrict__ mask,
    const float* __restrict__ trans,
    const float* __restrict__ startt,
    int B, int T)
{
    __shared__ float sE[2][CPB * RS];

    int tid = threadIdx.x;
    int b   = blockIdx.x >> 1;
    int k0  = (blockIdx.x & 1) * CPB;
    int k   = k0 + tid;
    size_t bT = (size_t)b * T;
    const float* emB = em + bT * 8;

    unsigned long long M2[8][4];
#pragma unroll
    for (int i = 0; i < 8; i++)
#pragma unroll
        for (int jj = 0; jj < 4; jj++)
            M2[i][jj] = pk2(__expf(__ldg(&trans[i * 8 + 2 * jj])),
                            __expf(__ldg(&trans[i * 8 + 2 * jj + 1])));

    float v[8];
#pragma unroll
    for (int j = 0; j < 8; j++) v[j] = 0.125f;

    float c = 0.0f, sp = 0.0f;
    int mcnt = 0;
    int pv = __ldg(&tags[bT + (k > 0 ? k * L - 1 : 0)]);

    float4 stg[8];
    // preload first tile (g = -OVLG)
#pragma unroll
    for (int m = 0; m < 8; m++) {
        int idx = m * CPB + tid;
        int r   = idx >> 3;
        int qq  = idx & 7;
        int tr  = (k0 + r) * L + 4 * (-OVLG);
        if (tr < 0) tr = 0;
        stg[m] = __ldg((const float4*)(emB + (size_t)tr * 8) + qq);
    }
#pragma unroll
    for (int m = 0; m < 8; m++) {
        int idx = m * CPB + tid;
        *((float4*)(sE[0] + (idx >> 3) * RS) + (idx & 7)) = stg[m];
    }
    __syncthreads();

    for (int g = -OVLG; g < L / 4; g++) {
        int cur = (g + OVLG) & 1;

        // issue next tile's LDGs before compute (latency hidden under compute)
        bool more = (g + 1 < L / 4);
        if (more) {
#pragma unroll
            for (int m = 0; m < 8; m++) {
                int idx = m * CPB + tid;
                int r   = idx >> 3;
                int qq  = idx & 7;
                int tr  = (k0 + r) * L + 4 * (g + 1);
                if (tr < 0) tr = 0;
                stg[m] = __ldg((const float4*)(emB + (size_t)tr * 8) + qq);
            }
        }

        int tb = k * L + 4 * g;
        const float* erow = sE[cur] + tid * RS;

        if (g == 0) {
            if (k == 0) {
                float e0[8];
                *(float4*)(e0)     = *((const float4*)erow);
                *(float4*)(e0 + 4) = *((const float4*)erow + 1);
                float s = 0.0f;
#pragma unroll
                for (int j = 0; j < 8; j++) {
                    v[j] = __expf(__ldg(&startt[j]) + e0[j]);
                    s += v[j];
                }
                c = __logf(s);
                float r = __fdividef(1.0f, s);
#pragma unroll
                for (int j = 0; j < 8; j++) v[j] *= r;
            } else {
                float s = v[0]+v[1]+v[2]+v[3]+v[4]+v[5]+v[6]+v[7];
                float r = __fdividef(1.0f, s);
                c = 0.0f;
#pragma unroll
                for (int j = 0; j < 8; j++) v[j] *= r;
            }
        }

        if (g >= 0) {
            int4 tg4 = __ldg((const int4*)(tags + bT + tb));
            int4 mk4 = __ldg((const int4*)(mask + bT + tb));
            int tgA[4] = {tg4.x, tg4.y, tg4.z, tg4.w};
            int mkA[4] = {mk4.x, mk4.y, mk4.z, mk4.w};
#pragma unroll
            for (int q = 0; q < 4; q++) {
                float e[8];
                *(float4*)(e)     = *((const float4*)erow + 2 * q);
                *(float4*)(e + 4) = *((const float4*)erow + 2 * q + 1);
                int tg = tgA[q];
                if (mkA[q] && (tb + q >= 1)) {
                    vstep(v, M2, e);
                    float es = e[0];
#pragma unroll
                    for (int j = 1; j < 8; j++) es = (tg == j) ? e[j] : es;
                    sp += es + __ldg(&trans[pv * 8 + tg]);
                    mcnt++;
                }
                pv = tg;
            }
        } else if (tb >= 0) {   // warm-up (k>0 only)
            int4 mk4 = __ldg((const int4*)(mask + bT + tb));
            int mkA[4] = {mk4.x, mk4.y, mk4.z, mk4.w};
#pragma unroll
            for (int q = 0; q < 4; q++) {
                float e[8];
                *(float4*)(e)     = *((const float4*)erow + 2 * q);
                *(float4*)(e + 4) = *((const float4*)erow + 2 * q + 1);
                if (mkA[q]) vstep(v, M2, e);
            }
        }

        // group-end rescale
        {
            float s = v[0]+v[1]+v[2]+v[3]+v[4]+v[5]+v[6]+v[7];
            float r = __fdividef(1.0f, s);
            c += __logf(s);
#pragma unroll
            for (int j = 0; j < 8; j++) v[j] *= r;
        }

        // store next tile into the alternate buffer, then one sync
        if (more) {
#pragma unroll
            for (int m = 0; m < 8; m++) {
                int idx = m * CPB + tid;
                *((float4*)(sE[cur ^ 1] + (idx >> 3) * RS) + (idx & 7)) = stg[m];
            }
            __syncthreads();
        }
    }

    size_t gidx = (size_t)b * KCH + k;
    g_c  [gidx] = c;
    g_sp [gidx] = sp;
    g_cnt[gidx] = mcnt;
    if (k == KCH - 1) {
#pragma unroll
        for (int j = 0; j < 8; j++) g_nf[b * 8 + j] = v[j];
    }
}

// ---------------------------------------------------------------------------
// Kernel 2: warp per batch. Lanes each sum 8 chunks of (c, sp, cnt), warp
// reduce, lane 0 adds end term and emits NLL.
// ---------------------------------------------------------------------------
__global__ void __launch_bounds__(256) crf_final(
    const float* __restrict__ em,
    const int* __restrict__ tags,
    const int* __restrict__ mask,
    const float* __restrict__ startt,
    const float* __restrict__ endt,
    float* __restrict__ out,
    int B, int T)
{
    int w    = (blockIdx.x * blockDim.x + threadIdx.x) >> 5;
    int lane = threadIdx.x & 31;
    if (w >= B) return;
    const int b = w;
    const unsigned FULL = 0xffffffffu;
    size_t bK = (size_t)b * KCH;

    float c = 0.0f, sp = 0.0f;
    int cnt = 0;
#pragma unroll
    for (int q = 0; q < 8; q++) {
        c   += __ldg(&g_c  [bK + lane + 32 * q]);
        sp  += __ldg(&g_sp [bK + lane + 32 * q]);
        cnt += __ldg(&g_cnt[bK + lane + 32 * q]);
    }
#pragma unroll
    for (int off = 16; off >= 1; off >>= 1) {
        c   += __shfl_xor_sync(FULL, c,   off);
        sp  += __shfl_xor_sync(FULL, sp,  off);
        cnt += __shfl_xor_sync(FULL, cnt, off);
    }

    if (lane == 0) {
        size_t bT = (size_t)b * T;
        float vsum = 0.0f;
#pragma unroll
        for (int j = 0; j < 8; j++)
            vsum += g_nf[b * 8 + j] * __expf(__ldg(&endt[j]));
        float logZ = c + __logf(vsum);

        cnt += (__ldg(&mask[bT]) != 0) ? 1 : 0;
        int last_valid = cnt - 1;
        int tag0  = __ldg(&tags[bT]);
        int lastt = __ldg(&tags[bT + last_valid]);
        float score = __ldg(&startt[tag0]) + __ldg(&em[bT * 8 + tag0])
                    + sp + __ldg(&endt[lastt]);
        out[b] = logZ - score;
    }
}

// ---------------------------------------------------------------------------
extern "C" void kernel_launch(void* const* d_in, const int* in_sizes, int n_in,
                              void* d_out, int out_size)
{
    const float* em     = (const float*)d_in[0];
    const int*   tags   = (const int*)d_in[1];
    const int*   mask   = (const int*)d_in[2];
    const float* trans  = (const float*)d_in[3];
    const float* startt = (const float*)d_in[4];
    const float* endt   = (const float*)d_in[5];

    int B = out_size;                 // 256
    int T = in_sizes[0] / (B * 8);    // 16384 (= KCH * L)

    int nblocks = B * (KCH / CPB);    // 512
    crf_chunk_vec<<<nblocks, CPB>>>(em, tags, mask, trans, startt, B, T);

    crf_final<<<(B * 32 + 255) / 256, 256>>>(em, tags, mask, startt, endt,
                                             (float*)d_out, B, T);
}